// round 11
// baseline (speedup 1.0000x reference)
#include <cuda_runtime.h>
#include <cstdint>

#define DIM     4096
#define NEXP    64
#define NTOK    16384
#define KSPLIT  8
#define KCHUNK  (DIM / KSPLIT)     // 512
#define BM      128
#define BK      16
#define NTILES  (KCHUNK / BK)      // 32
#define GTHREADS 128
#define XS_STRIDE (BM + 4)         // 132: multiple of 4 (keeps LDS.128 aligned), conflict-managed
#define WS_STRIDE (NEXP + 4)       // 68

// Scratch: KSPLIT partial logit planes [N, E]. 8*16384*64*4B = 32 MB, static device global
// (allowed; no runtime allocation).
__device__ float g_partial[(size_t)KSPLIT * NTOK * NEXP];

// ---------------- PTX helpers ----------------
__device__ __forceinline__ void cp_async4(uint32_t dst, const float* src) {
    asm volatile("cp.async.ca.shared.global [%0], [%1], 4;" :: "r"(dst), "l"(src));
}
__device__ __forceinline__ void cp_commit() {
    asm volatile("cp.async.commit_group;" ::: "memory");
}
__device__ __forceinline__ void cp_wait0() {
    asm volatile("cp.async.wait_group 0;" ::: "memory");
}
__device__ __forceinline__ void cp_wait1() {
    asm volatile("cp.async.wait_group 1;" ::: "memory");
}
// duplicate a float into both halves of a packed f32x2
__device__ __forceinline__ unsigned long long dup_f32x2(float v) {
    unsigned long long r;
    asm("mov.b64 %0, {%1, %1};" : "=l"(r) : "f"(v));
    return r;
}
// packed dual-FMA: d.lo += a.lo*b.lo ; d.hi += a.hi*b.hi  (Blackwell FFMA2)
__device__ __forceinline__ void fma_f32x2(unsigned long long& d,
                                          unsigned long long a,
                                          unsigned long long b) {
    asm("fma.rn.f32x2 %0, %1, %2, %0;" : "+l"(d) : "l"(a), "l"(b));
}

// ---------------- Pass 1: logits GEMM (x @ W^T), K-split partials ----------------
// CTA: 128 tokens x 64 experts, k-chunk = 512 per blockIdx.y.
// Thread tile: 4 tokens x 16 experts, accumulators packed as f32x2 over expert pairs.
__global__ void __launch_bounds__(GTHREADS)
gate_gemm(const float* __restrict__ x, const float* __restrict__ Wm, int N) {
    __shared__ __align__(16) float xs[2][BK][XS_STRIDE];  // transposed: xs[k][token]
    __shared__ __align__(16) float ws[2][BK][WS_STRIDE];  // transposed: ws[k][expert]

    const int tid = threadIdx.x;
    const int m0  = blockIdx.x * BM;
    const long long k0 = (long long)blockIdx.y * KCHUNK;

    // loader mapping: lc = k within tile (coalesced 64B runs), lr = row slice
    const int lc = tid & 15;
    const int lr = tid >> 4;

    const float* xsrc = x  + (long long)m0 * DIM + k0 + lc;
    const float* wsrc = Wm + k0 + lc;

    // compute mapping: lane -> 4 consecutive tokens, warp -> 16 consecutive experts
    const int lane = tid & 31;
    const int wrp  = tid >> 5;
    const int t0   = lane * 4;
    const int e0   = wrp * 16;

    unsigned long long acc[4][8];
#pragma unroll
    for (int t = 0; t < 4; t++)
#pragma unroll
        for (int j = 0; j < 8; j++) acc[t][j] = 0ULL;

    // prefetch tile 0
#pragma unroll
    for (int p = 0; p < 16; p++) {
        int row = lr + p * 8;
        cp_async4((uint32_t)__cvta_generic_to_shared(&xs[0][lc][row]),
                  xsrc + (long long)row * DIM);
    }
#pragma unroll
    for (int p = 0; p < 8; p++) {
        int e = lr + p * 8;
        cp_async4((uint32_t)__cvta_generic_to_shared(&ws[0][lc][e]),
                  wsrc + (long long)e * DIM);
    }
    cp_commit();

    for (int tile = 0; tile < NTILES; tile++) {
        const int cur = tile & 1;
        if (tile + 1 < NTILES) {
            const int nxt = cur ^ 1;
            const float* xn = xsrc + (long long)(tile + 1) * BK;
            const float* wn = wsrc + (long long)(tile + 1) * BK;
#pragma unroll
            for (int p = 0; p < 16; p++) {
                int row = lr + p * 8;
                cp_async4((uint32_t)__cvta_generic_to_shared(&xs[nxt][lc][row]),
                          xn + (long long)row * DIM);
            }
#pragma unroll
            for (int p = 0; p < 8; p++) {
                int e = lr + p * 8;
                cp_async4((uint32_t)__cvta_generic_to_shared(&ws[nxt][lc][e]),
                          wn + (long long)e * DIM);
            }
            cp_commit();
            cp_wait1();   // previous group (tile `tile`) complete
        } else {
            cp_wait0();
        }
        __syncthreads();

#pragma unroll
        for (int k = 0; k < BK; k++) {
            const float4 xv = *reinterpret_cast<const float4*>(&xs[cur][k][t0]);
            const ulonglong2 w0 = *reinterpret_cast<const ulonglong2*>(&ws[cur][k][e0]);
            const ulonglong2 w1 = *reinterpret_cast<const ulonglong2*>(&ws[cur][k][e0 + 4]);
            const ulonglong2 w2 = *reinterpret_cast<const ulonglong2*>(&ws[cur][k][e0 + 8]);
            const ulonglong2 w3 = *reinterpret_cast<const ulonglong2*>(&ws[cur][k][e0 + 12]);
            unsigned long long wp[8] = {w0.x, w0.y, w1.x, w1.y, w2.x, w2.y, w3.x, w3.y};
            unsigned long long xd[4] = {dup_f32x2(xv.x), dup_f32x2(xv.y),
                                        dup_f32x2(xv.z), dup_f32x2(xv.w)};
#pragma unroll
            for (int t = 0; t < 4; t++)
#pragma unroll
                for (int j = 0; j < 8; j++)
                    fma_f32x2(acc[t][j], xd[t], wp[j]);
        }
        __syncthreads();  // protect cur buffer before it is re-filled next+1 iteration
    }

    // epilogue: write partial logits plane for this k-split
    float* pout = g_partial + (size_t)blockIdx.y * N * NEXP;
#pragma unroll
    for (int t = 0; t < 4; t++) {
        const long long row = m0 + t0 + t;
        unsigned long long* o =
            reinterpret_cast<unsigned long long*>(pout + row * NEXP + e0);
#pragma unroll
        for (int j = 0; j < 8; j++) o[j] = acc[t][j];
    }
}

// ---------------- Pass 2: reduce K-split partials, top-2, softmax, scatter ----------------
// One warp per token. lane owns experts {lane, lane+32}.
__global__ void topk_softmax(float* __restrict__ out, int N, int with_idx) {
    const int tok  = blockIdx.x * (blockDim.x >> 5) + (threadIdx.x >> 5);
    const int lane = threadIdx.x & 31;
    if (tok >= N) return;

    float va = 0.0f, vb = 0.0f;
#pragma unroll
    for (int s = 0; s < KSPLIT; s++) {
        const float* ps = g_partial + (size_t)s * N * NEXP + (size_t)tok * NEXP;
        va += ps[lane];
        vb += ps[lane + 32];
    }

    // local ordered top-2 (JAX tie-break: equal values -> lower index first)
    float v1, v2; int i1, i2;
    if (va >= vb) { v1 = va; i1 = lane;      v2 = vb; i2 = lane + 32; }
    else          { v1 = vb; i1 = lane + 32; v2 = va; i2 = lane;      }

    // butterfly merge -> all lanes converge to global top-2
#pragma unroll
    for (int off = 16; off > 0; off >>= 1) {
        float u1 = __shfl_xor_sync(0xffffffffu, v1, off);
        int   j1 = __shfl_xor_sync(0xffffffffu, i1, off);
        float u2 = __shfl_xor_sync(0xffffffffu, v2, off);
        int   j2 = __shfl_xor_sync(0xffffffffu, i2, off);
        bool keep1 = (v1 > u1) || (v1 == u1 && i1 < j1);
        if (keep1) {
            bool k2 = (v2 > u1) || (v2 == u1 && i2 < j1);
            if (!k2) { v2 = u1; i2 = j1; }
        } else {
            bool k2 = (v1 > u2) || (v1 == u2 && i1 < j2);
            if (k2) { v2 = v1; i2 = i1; } else { v2 = u2; i2 = j2; }
            v1 = u1; i1 = j1;
        }
    }

    // softmax over the two selected logits (v1 is the max)
    const float e2 = expf(v2 - v1);
    const float s  = 1.0f / (1.0f + e2);
    const float w1 = s;
    const float w2 = e2 * s;

    const float oa = (lane == i1)        ? w1 : ((lane == i2)        ? w2 : 0.0f);
    const float ob = ((lane + 32) == i1) ? w1 : (((lane + 32) == i2) ? w2 : 0.0f);
    out[(size_t)tok * NEXP + lane]      = oa;
    out[(size_t)tok * NEXP + lane + 32] = ob;

    if (with_idx && lane == 0) {
        float* oi = out + (size_t)N * NEXP + (size_t)tok * 2;
        oi[0] = (float)i1;
        oi[1] = (float)i2;
    }
}

// ---------------- launch ----------------
extern "C" void kernel_launch(void* const* d_in, const int* in_sizes, int n_in,
                              void* d_out, int out_size) {
    const float* x  = (const float*)d_in[0];   // [N, 4096]
    const float* Wm = (const float*)d_in[1];   // [64, 4096]
    const int N = in_sizes[0] / DIM;           // 16384

    dim3 grid(N / BM, KSPLIT);
    gate_gemm<<<grid, GTHREADS>>>(x, Wm, N);

    // Output layout: full_weights [N,64] (float32), optionally followed by
    // top_k_indices [N,2] written as floats (reference tuple concatenated).
    const int with_idx = (out_size >= N * NEXP + N * 2) ? 1 : 0;
    const int blocks = (N + 7) / 8;            // 8 warps (=8 tokens) per 256-thread block
    topk_softmax<<<blocks, 256>>>((float*)d_out, N, with_idx);
}

// round 15
// speedup vs baseline: 1.0241x; 1.0241x over previous
#include <cuda_runtime.h>
#include <cstdint>

#define DIM     4096
#define NEXP    64
#define BM      128
#define BK      32
#define NITER   (DIM / BK)       // 128
#define THREADS 256
#define APAD    36               // row stride (floats): 144B, 16B-aligned, 4-bank shift/row
#define ASZ     (BM * APAD)      // 4608 floats
#define BSZ     (NEXP * APAD)    // 2304 floats
#define STAGEF  (ASZ + BSZ)      // 6912 floats = 27648 B
#define NSTAGE  4
#define LPAD    68               // logits overlay row stride (16B-aligned)
#define DYN_SMEM (NSTAGE * STAGEF * 4)   // 110592 B

// ---------------- helpers ----------------
__device__ __forceinline__ uint32_t sptr(const void* p) {
    return (uint32_t)__cvta_generic_to_shared(p);
}
__device__ __forceinline__ void cpa16(uint32_t d, const float* s) {
    asm volatile("cp.async.cg.shared.global [%0], [%1], 16;" :: "r"(d), "l"(s));
}
__device__ __forceinline__ void cpc()  { asm volatile("cp.async.commit_group;" ::: "memory"); }
__device__ __forceinline__ void cpw2() { asm volatile("cp.async.wait_group 2;" ::: "memory"); }

__device__ __forceinline__ uint32_t tfhi(float v) {
    uint32_t r; asm("cvt.rna.tf32.f32 %0, %1;" : "=r"(r) : "f"(v)); return r;
}
// 3-term split: v = hi + lo (each exactly representable in tf32)
__device__ __forceinline__ void split(float v, uint32_t& h, uint32_t& l) {
    h = tfhi(v);
    l = tfhi(v - __uint_as_float(h));
}
__device__ __forceinline__ void mma8(float* d, const uint32_t* a, const uint32_t* b) {
    asm volatile(
        "mma.sync.aligned.m16n8k8.row.col.f32.tf32.tf32.f32 "
        "{%0,%1,%2,%3}, {%4,%5,%6,%7}, {%8,%9}, {%0,%1,%2,%3};"
        : "+f"(d[0]), "+f"(d[1]), "+f"(d[2]), "+f"(d[3])
        : "r"(a[0]), "r"(a[1]), "r"(a[2]), "r"(a[3]), "r"(b[0]), "r"(b[1]));
}

__device__ __forceinline__ void load_stage(float* sm, int buf, const float* x,
                                           const float* W, int m0, int k0, int tid) {
    float* As = sm + buf * STAGEF;
    float* Bs = As + ASZ;
#pragma unroll
    for (int p = 0; p < 4; p++) {                 // A: 128 rows x 128B
        int idx = tid + p * THREADS;
        int row = idx >> 3, c = idx & 7;
        cpa16(sptr(As + row * APAD + c * 4),
              x + (size_t)(m0 + row) * DIM + k0 + c * 4);
    }
#pragma unroll
    for (int p = 0; p < 2; p++) {                 // B: 64 rows x 128B
        int idx = tid + p * THREADS;
        int row = idx >> 3, c = idx & 7;
        cpa16(sptr(Bs + row * APAD + c * 4),
              W + (size_t)row * DIM + k0 + c * 4);
    }
}

// ---------------- fused gate kernel ----------------
__global__ void __launch_bounds__(THREADS, 1)
gate_mma(const float* __restrict__ x, const float* __restrict__ W,
         float* __restrict__ out, int N, int with_idx)
{
    extern __shared__ __align__(16) float sm[];
    const int tid  = threadIdx.x;
    const int wid  = tid >> 5;
    const int lane = tid & 31;
    const int gid  = lane >> 2;          // 0..7
    const int tig  = lane & 3;           // 0..3
    const int wm   = (wid & 3) * 32;     // warp M offset (4 M-warps)
    const int wn   = (wid >> 2) * 32;    // warp N offset (2 N-warps)
    const int m0   = blockIdx.x * BM;

    float acc[2][4][4];
#pragma unroll
    for (int mt = 0; mt < 2; mt++)
#pragma unroll
        for (int nt = 0; nt < 4; nt++)
#pragma unroll
            for (int q = 0; q < 4; q++) acc[mt][nt][q] = 0.0f;

    // prologue: stages 0..2 in flight
#pragma unroll
    for (int s = 0; s < NSTAGE - 1; s++) {
        load_stage(sm, s, x, W, m0, s * BK, tid);
        cpc();
    }

    for (int it = 0; it < NITER; it++) {
        const int buf = it & (NSTAGE - 1);
        cpw2();                       // stage `it` complete (<=2 groups pending)
        __syncthreads();

        if (it + NSTAGE - 1 < NITER)
            load_stage(sm, (it + NSTAGE - 1) & (NSTAGE - 1), x, W, m0,
                       (it + NSTAGE - 1) * BK, tid);
        cpc();                        // one group per iteration (may be empty)

        const float* As = sm + buf * STAGEF;
        const float* Bs = As + ASZ;
        const float* pa = As + (wm + gid) * APAD;
        const float* pb = Bs + (wn + gid) * APAD;

#pragma unroll
        for (int ks = 0; ks < 4; ks++) {          // 4 x k8 per BK=32
            const int k = ks * 8 + tig;
            uint32_t ah[2][4], al[2][4], bh[4][2], bl[4][2];
#pragma unroll
            for (int mt = 0; mt < 2; mt++) {
                const float* q = pa + mt * 16 * APAD;
                split(q[k],                ah[mt][0], al[mt][0]);
                split(q[8 * APAD + k],     ah[mt][1], al[mt][1]);
                split(q[k + 4],            ah[mt][2], al[mt][2]);
                split(q[8 * APAD + k + 4], ah[mt][3], al[mt][3]);
            }
#pragma unroll
            for (int nt = 0; nt < 4; nt++) {
                const float* q = pb + nt * 8 * APAD;
                split(q[k],     bh[nt][0], bl[nt][0]);
                split(q[k + 4], bh[nt][1], bl[nt][1]);
            }
            // 3 terms, each swept across all 8 acc tiles (dependency distance >= 8 mma)
#pragma unroll
            for (int mt = 0; mt < 2; mt++)
#pragma unroll
                for (int nt = 0; nt < 4; nt++) mma8(acc[mt][nt], ah[mt], bh[nt]);
#pragma unroll
            for (int mt = 0; mt < 2; mt++)
#pragma unroll
                for (int nt = 0; nt < 4; nt++) mma8(acc[mt][nt], ah[mt], bl[nt]);
#pragma unroll
            for (int mt = 0; mt < 2; mt++)
#pragma unroll
                for (int nt = 0; nt < 4; nt++) mma8(acc[mt][nt], al[mt], bh[nt]);
        }
    }

    // ---------------- epilogue: logits -> top-2 -> softmax -> scatter ----------------
    __syncthreads();                  // all stage reads done before overlay
    float* ls = sm;                   // overlay: [128][LPAD] logits

#pragma unroll
    for (int mt = 0; mt < 2; mt++)
#pragma unroll
        for (int nt = 0; nt < 4; nt++) {
            const int r = wm + mt * 16 + gid;
            const int c = wn + nt * 8 + tig * 2;
            *(float2*)(ls + r * LPAD + c)       = make_float2(acc[mt][nt][0], acc[mt][nt][1]);
            *(float2*)(ls + (r + 8) * LPAD + c) = make_float2(acc[mt][nt][2], acc[mt][nt][3]);
        }
    __syncthreads();

    if (tid < BM) {
        float* row = ls + tid * LPAD;
        float v1 = -3.4e38f, v2 = -3.4e38f;
        int   i1 = 0, i2 = 0;
#pragma unroll
        for (int j = 0; j < NEXP; j++) {          // ties -> lower index (JAX top_k)
            float v = row[j];
            if (v > v1)      { v2 = v1; i2 = i1; v1 = v; i1 = j; }
            else if (v > v2) { v2 = v;  i2 = j; }
        }
        const float e2 = expf(v2 - v1);           // v1 >= v2: stable
        const float ss = 1.0f / (1.0f + e2);
        const float w1 = ss, w2 = e2 * ss;
#pragma unroll
        for (int j = 0; j < NEXP; j++) row[j] = 0.0f;
        row[i1] = w1;
        row[i2] = w2;
        if (with_idx) {
            *(float2*)(out + (size_t)N * NEXP + (size_t)(m0 + tid) * 2) =
                make_float2((float)i1, (float)i2);
        }
    }
    __syncthreads();

    // coalesced copy of the 128x64 weight block
    for (int q = tid; q < BM * NEXP / 4; q += THREADS) {
        const int i = q * 4;
        const int r = i >> 6, c = i & 63;
        float4 v = *(const float4*)(ls + r * LPAD + c);
        *(float4*)(out + (size_t)m0 * NEXP + i) = v;
    }
}

// ---------------- launch ----------------
extern "C" void kernel_launch(void* const* d_in, const int* in_sizes, int n_in,
                              void* d_out, int out_size) {
    const float* x  = (const float*)d_in[0];   // [N, 4096]
    const float* Wm = (const float*)d_in[1];   // [64, 4096]
    const int N = in_sizes[0] / DIM;           // 16384

    cudaFuncSetAttribute(gate_mma, cudaFuncAttributeMaxDynamicSharedMemorySize,
                         DYN_SMEM);
    const int with_idx = (out_size >= N * NEXP + N * 2) ? 1 : 0;
    gate_mma<<<N / BM, THREADS, DYN_SMEM>>>(x, Wm, (float*)d_out, N, with_idx);
}